// round 16
// baseline (speedup 1.0000x reference)
#include <cuda_runtime.h>
#include <cuda_bf16.h>

// RoiAlign: fm (1,256,50,50) f32, proposals (1024,4) f32 -> out (1024,256,7,7) f32
// Reference double-applies SCALE => /256 and clamps roi_w/h >= 1 (wh<=200 means
// the clamp ALWAYS fires, roi_w=roi_h=1), so all sample coords lie in [0,3.23]
// and every box reads only fm[:, 0:5, 0:5].
// This kernel is the measured-best R1 skeleton (256 threads = 256 channels,
// 1 box/block, acc[7][7] in regs, 4-chunk staged coalesced store) with exactly
// ONE change: the 16 scattered per-thread LDGs are replaced by a cooperative
// coalesced fill of the shared 5x5 hot patch + conflict-free LDS preload.
// Runtime-validated; block-uniform gmem fallback if a patch exceeds [0,4].

#define C_CH  256
#define HH    50
#define WW    50
#define OUTSZ 7
#define SSAMP 14   // OUT * SR
#define SPAN  5    // fixed patch rows/cols 0..4
#define BTH   256

__global__ __launch_bounds__(BTH, 2)
void roi_align_kernel(const float* __restrict__ fm,
                      const float* __restrict__ proposals,
                      float* __restrict__ out)
{
    const int n   = blockIdx.x;
    const int tid = threadIdx.x;

    __shared__ float s_patch[C_CH * 25];                 // 25.6 KB hot patch
    __shared__ __align__(16) float s_stage[64 * 49];     // 12.5 KB chunk stage
    __shared__ float s_h[2 * SSAMP], s_l[2 * SSAMP];
    __shared__ int   s_a0[2 * SSAMP], s_a1[2 * SSAMP];
    __shared__ float sWy[OUTSZ][SPAN], sWx[OUTSZ][SPAN];
    __shared__ int   s_ok;

    // ---------- cooperative coalesced fill of the 5x5 hot patch ----------
    // s_patch[ch*25 + k] = fm[ch, k/5, k%5]; 6400 floats, 25 iters, full unroll
    // gives 25 independent LDGs in flight per thread.
    {
        #pragma unroll
        for (int j = 0; j < 25; j++) {
            int i  = j * BTH + tid;
            int ch = i / 25;
            int k  = i - ch * 25;
            s_patch[i] = fm[ch * (HH * WW) + (k / 5) * WW + (k % 5)];
        }
    }

    // ---------- per-box axis sample params: 28 threads ----------
    if (tid < 2 * SSAMP) {
        const bool isY = tid < SSAMP;
        const int  s   = isY ? tid : tid - SSAMP;
        float4 p = reinterpret_cast<const float4*>(proposals)[n];
        const float sc = 0.0625f;
        float x1 = (p.x * sc) * sc, y1v = (p.y * sc) * sc;
        float x2 = (p.z * sc) * sc, y2v = (p.w * sc) * sc;
        float roiw = fmaxf(x2 - x1, 1.0f);
        float roih = fmaxf(y2v - y1v, 1.0f);
        float g = ((float)s + 0.5f) * 0.5f;              // (s+0.5)/SR
        float v = isY ? (y1v + (roih * (1.0f / 7.0f)) * g)
                      : (x1  + (roiw * (1.0f / 7.0f)) * g);
        const int L = HH;                                 // H == W == 50
        bool valid = (v >= -1.0f) && (v <= (float)L);
        float vc = fminf(fmaxf(v, 0.0f), (float)(L - 1));
        int i0 = min((int)floorf(vc), L - 1);
        int i1 = min(i0 + 1, L - 1);
        float l = vc - (float)i0;
        float h = 1.0f - l;
        if (!valid) { h = 0.0f; l = 0.0f; }
        s_a0[tid] = i0; s_a1[tid] = i1; s_h[tid] = h; s_l[tid] = l;
    }
    __syncthreads();                                      // B1

    // ---------- combined separable bin weights (base 0): 14 threads ----------
    if (tid < 2 * OUTSZ) {
        const bool isY = tid < OUTSZ;
        const int  o   = isY ? tid : tid - OUTSZ;
        const int  off = isY ? 0 : SSAMP;
        float w[SPAN] = {0.f, 0.f, 0.f, 0.f, 0.f};
        #pragma unroll
        for (int k = 0; k < 2; k++) {
            int s = off + 2 * o + k;
            w[min(s_a0[s], SPAN - 1)] += 0.5f * s_h[s];
            w[min(s_a1[s], SPAN - 1)] += 0.5f * s_l[s];
        }
        #pragma unroll
        for (int q = 0; q < SPAN; q++) {
            if (isY) sWy[o][q] = w[q]; else sWx[o][q] = w[q];
        }
    } else if (tid == 32) {
        int mx = -1;
        #pragma unroll
        for (int s = 0; s < 2 * SSAMP; s++) mx = max(mx, s_a1[s]);
        s_ok = (mx <= SPAN - 1) ? 1 : 0;
    }
    __syncthreads();                                      // B2

    if (s_ok) {
        // ---------- fast separable path: thread = channel, acc in regs ----------
        float r[25];
        #pragma unroll
        for (int k = 0; k < 25; k++) r[k] = s_patch[tid * 25 + k];

        float acc[OUTSZ][OUTSZ];
        #pragma unroll
        for (int a = 0; a < OUTSZ; a++)
            #pragma unroll
            for (int b = 0; b < OUTSZ; b++) acc[a][b] = 0.0f;

        #pragma unroll
        for (int y = 0; y < SPAN; y++) {
            float sx[OUTSZ];
            #pragma unroll
            for (int o = 0; o < OUTSZ; o++)
                sx[o] = r[y*5+0] * sWx[o][0] + r[y*5+1] * sWx[o][1]
                      + r[y*5+2] * sWx[o][2] + r[y*5+3] * sWx[o][3]
                      + r[y*5+4] * sWx[o][4];
            #pragma unroll
            for (int oy = 0; oy < OUTSZ; oy++) {
                float wyv = sWy[oy][y];
                #pragma unroll
                for (int ox = 0; ox < OUTSZ; ox++)
                    acc[oy][ox] += wyv * sx[ox];
            }
        }

        // ---------- R1's proven 4-chunk staged, coalesced store ----------
        #pragma unroll 1
        for (int chunk = 0; chunk < 4; chunk++) {
            __syncthreads();
            if ((tid >> 6) == chunk) {
                int cl = tid & 63;
                #pragma unroll
                for (int oy = 0; oy < OUTSZ; oy++)
                    #pragma unroll
                    for (int ox = 0; ox < OUTSZ; ox++)
                        s_stage[cl * 49 + oy * 7 + ox] = acc[oy][ox];
            }
            __syncthreads();
            float4* dst = reinterpret_cast<float4*>(
                out + ((size_t)n * C_CH + (size_t)chunk * 64) * 49);
            const float4* src = reinterpret_cast<const float4*>(s_stage);
            for (int i = tid; i < (64 * 49) / 4; i += BTH)
                dst[i] = src[i];
        }
    } else {
        // ---------- general fallback (block-uniform, never hot here) ----------
        const float* fmc = fm + (size_t)tid * (HH * WW);
        float* outc = out + ((size_t)n * C_CH + tid) * 49;
        for (int oy = 0; oy < OUTSZ; oy++) {
            for (int ox = 0; ox < OUTSZ; ox++) {
                float a = 0.0f;
                #pragma unroll
                for (int ky = 0; ky < 2; ky++) {
                    int sy = 2 * oy + ky;
                    int y0 = s_a0[sy] * WW, y1i = s_a1[sy] * WW;
                    float hy = s_h[sy], ly = s_l[sy];
                    #pragma unroll
                    for (int kx = 0; kx < 2; kx++) {
                        int sxi = SSAMP + 2 * ox + kx;
                        int x0 = s_a0[sxi], x1i = s_a1[sxi];
                        float hx = s_h[sxi], lx = s_l[sxi];
                        a += hy * (hx * fmc[y0 + x0]  + lx * fmc[y0 + x1i])
                           + ly * (hx * fmc[y1i + x0] + lx * fmc[y1i + x1i]);
                    }
                }
                outc[oy * 7 + ox] = a * 0.25f;
            }
        }
        // keep barrier count uniform with the fast path
        #pragma unroll 1
        for (int chunk = 0; chunk < 4; chunk++) { __syncthreads(); __syncthreads(); }
    }
}

extern "C" void kernel_launch(void* const* d_in, const int* in_sizes, int n_in,
                              void* d_out, int out_size) {
    const float* fm    = (const float*)d_in[0];   // (1,256,50,50) f32
    const float* props = (const float*)d_in[1];   // (1024,4) f32
    float* out         = (float*)d_out;           // (1024,256,7,7) f32
    int N = in_sizes[1] / 4;
    roi_align_kernel<<<N, BTH>>>(fm, props, out);
}